// round 15
// baseline (speedup 1.0000x reference)
#include <cuda_runtime.h>
#include <cuda_fp16.h>
#include <math.h>
#include <cstdint>

// ---------------------------------------------------------------------------
// MiniBlock: x + attn(ln1(x)); then + mlp(ln2(.))
// B=4, T=2048, C=1024, H=16, D=64, FF=4096.
// GEMMs: mma.sync fp16 fp32-acc, 128x128x64 tiles (legacy-HMMA issue floor).
// Attention: flash, 128-row q-tiles, f16x2 ex2 softmax, deferred row-sum,
// V prefetch under the barrier. Prep (weight transpose + ln1) fused into
// one launch.
// ---------------------------------------------------------------------------

#define B_NUM 4
#define T_SEQ 2048
#define C_DIM 1024
#define H_NUM 16
#define D_HEAD 64
#define FF_DIM 4096
#define M_ROWS (B_NUM * T_SEQ)   // 8192
#define QKV_N (3 * C_DIM)        // 3072

// ---------------- scratch (device globals) ----------------------------------
__device__ __half g_a  [M_ROWS * C_DIM];
__device__ __half g_qkv[M_ROWS * QKV_N];
__device__ __half g_at [M_ROWS * C_DIM];
__device__ __half g_ffh[M_ROWS * FF_DIM];
__device__ float  g_x2 [M_ROWS * C_DIM];

__device__ __half g_wqkv[QKV_N * C_DIM];
__device__ __half g_wo[C_DIM * C_DIM];
__device__ __half g_w1[FF_DIM * C_DIM];
__device__ __half g_w2[C_DIM * FF_DIM];

// ---------------- PTX helpers ------------------------------------------------
__device__ __forceinline__ uint32_t smem_u32(const void* p) {
    uint32_t a;
    asm("{ .reg .u64 t; cvta.to.shared.u64 t, %1; cvt.u32.u64 %0, t; }" : "=r"(a) : "l"(p));
    return a;
}
__device__ __forceinline__ void cp16(uint32_t dst, const void* src) {
    asm volatile("cp.async.cg.shared.global [%0], [%1], 16;" :: "r"(dst), "l"(src));
}
__device__ __forceinline__ void cp_commit() { asm volatile("cp.async.commit_group;" ::: "memory"); }
template <int N> __device__ __forceinline__ void cp_wait() {
    asm volatile("cp.async.wait_group %0;" :: "n"(N) : "memory");
}
__device__ __forceinline__ void ldsm4(uint32_t r[4], uint32_t addr) {
    asm volatile("ldmatrix.sync.aligned.m8n8.x4.shared.b16 {%0,%1,%2,%3}, [%4];"
                 : "=r"(r[0]), "=r"(r[1]), "=r"(r[2]), "=r"(r[3]) : "r"(addr));
}
__device__ __forceinline__ void mma_f16(float c[4], const uint32_t a[4],
                                        uint32_t b0, uint32_t b1) {
    asm volatile(
        "mma.sync.aligned.m16n8k16.row.col.f32.f16.f16.f32 "
        "{%0,%1,%2,%3}, {%4,%5,%6,%7}, {%8,%9}, {%0,%1,%2,%3};"
        : "+f"(c[0]), "+f"(c[1]), "+f"(c[2]), "+f"(c[3])
        : "r"(a[0]), "r"(a[1]), "r"(a[2]), "r"(a[3]), "r"(b0), "r"(b1));
}
__device__ __forceinline__ uint32_t packh2(float a, float b) {
    __half2 h = __floats2half2_rn(a, b);
    return *(uint32_t*)&h;
}
__device__ __forceinline__ float ex2(float x) {
    float y;
    asm("ex2.approx.f32 %0, %1;" : "=f"(y) : "f"(x));
    return y;
}
__device__ __forceinline__ uint32_t h2ex2(uint32_t x) {
    uint32_t y;
    asm("ex2.approx.f16x2 %0, %1;" : "=r"(y) : "r"(x));
    return y;
}

#define SWZ(x) ((x) ^ (((x) >> 3) & 0x70))

// ---------------------------------------------------------------------------
// fp16 GEMM: C[M,N] = A[M,K] @ B^T   (B stored [N,K] fp16)
// Block 128x128x64, 256 thr (8 warps 2x4), warp tile 64x32.
// 3-stage cp.async pipeline, 2 CTAs/SM.  (At the mma.sync issue floor.)
// ---------------------------------------------------------------------------
static constexpr int GEMM_STAGE = 32768;
static constexpr int GEMM_SMEM  = 3 * GEMM_STAGE;  // 98304

template <int RELU, int OUT_HALF>
__global__ __launch_bounds__(256, 2)
void gemm_mma(const __half* __restrict__ A, const __half* __restrict__ B,
              const float* __restrict__ bias, const float* __restrict__ res,
              float* __restrict__ Cf, __half* __restrict__ Oh,
              int N, int K) {
    extern __shared__ __align__(1024) char smem[];
    const uint32_t sb = smem_u32(smem);
    const int tid = threadIdx.x;
    const int lane = tid & 31;
    const int wid = tid >> 5;
    const int warp_m = wid >> 2;
    const int warp_n = wid & 3;
    const int n0 = blockIdx.x * 128;
    const int m0 = blockIdx.y * 128;
    const int nc = K >> 6;

    const int lrow = tid >> 1;
    const int lhalf = (tid & 1) * 64;
    const char* pa = (const char*)(A + (size_t)(m0 + lrow) * K) + lhalf;
    const char* pb = (const char*)(B + (size_t)(n0 + lrow) * K) + lhalf;

    auto issue = [&](int c) {
        uint32_t base = sb + (uint32_t)(c % 3) * GEMM_STAGE;
        size_t koff = (size_t)(c << 6) * 2;
#pragma unroll
        for (int j = 0; j < 4; j++) {
            uint32_t so = SWZ((uint32_t)(lrow * 128 + lhalf + j * 16));
            cp16(base + so,         pa + koff + j * 16);
            cp16(base + 16384 + so, pb + koff + j * 16);
        }
        cp_commit();
    };

    issue(0);
    if (nc > 1) issue(1);

    const int rowA = (lane & 7) + ((lane >> 3) & 1) * 8;
    const int colA = (lane >> 4) * 16;
    const int rowB = (lane & 7) + (lane >> 4) * 8;
    const int colB = ((lane >> 3) & 1) * 16;

    float acc[4][4][4];
#pragma unroll
    for (int a = 0; a < 4; a++)
#pragma unroll
        for (int b = 0; b < 4; b++)
#pragma unroll
            for (int r = 0; r < 4; r++) acc[a][b][r] = 0.f;

    for (int c = 0; c < nc; c++) {
        if (c + 1 < nc) cp_wait<1>(); else cp_wait<0>();
        __syncthreads();
        if (c + 2 < nc) issue(c + 2);

        uint32_t stb = sb + (uint32_t)(c % 3) * GEMM_STAGE;
#pragma unroll
        for (int ks = 0; ks < 4; ks++) {
            uint32_t ah[4][4], bh[2][4];
#pragma unroll
            for (int mt = 0; mt < 4; mt++) {
                uint32_t sw = SWZ((uint32_t)((warp_m * 64 + mt * 16 + rowA) * 128 + ks * 32 + colA));
                ldsm4(ah[mt], stb + sw);
            }
#pragma unroll
            for (int np = 0; np < 2; np++) {
                uint32_t sw = SWZ((uint32_t)((warp_n * 32 + np * 16 + rowB) * 128 + ks * 32 + colB));
                ldsm4(bh[np], stb + 16384 + sw);
            }
#pragma unroll
            for (int mt = 0; mt < 4; mt++)
#pragma unroll
                for (int nt = 0; nt < 4; nt++)
                    mma_f16(acc[mt][nt], ah[mt],
                            bh[nt >> 1][(nt & 1) * 2], bh[nt >> 1][(nt & 1) * 2 + 1]);
        }
    }

    const int rbase = m0 + warp_m * 64 + (lane >> 2);
    const int cbase = n0 + warp_n * 32 + (lane & 3) * 2;
#pragma unroll
    for (int mt = 0; mt < 4; mt++) {
#pragma unroll
        for (int nt = 0; nt < 4; nt++) {
            int col = cbase + nt * 8;
#pragma unroll
            for (int half = 0; half < 2; half++) {
                int row = rbase + mt * 16 + half * 8;
                float v0 = acc[mt][nt][half * 2 + 0];
                float v1 = acc[mt][nt][half * 2 + 1];
                if (bias) {
                    float2 b2 = *(const float2*)(bias + col);
                    v0 += b2.x; v1 += b2.y;
                }
                if (res) {
                    float2 r2 = *(const float2*)(res + (size_t)row * N + col);
                    v0 += r2.x; v1 += r2.y;
                }
                if (RELU) { v0 = fmaxf(v0, 0.f); v1 = fmaxf(v1, 0.f); }
                if (OUT_HALF) {
                    __half2 h = __floats2half2_rn(v0, v1);
                    *(__half2*)(Oh + (size_t)row * N + col) = h;
                } else {
                    float2 o2; o2.x = v0; o2.y = v1;
                    *(float2*)(Cf + (size_t)row * N + col) = o2;
                }
            }
        }
    }
}

// ---------------------------------------------------------------------------
// LayerNorm -> fp16, callable as device helper (one 256-thread block per row).
// ---------------------------------------------------------------------------
__device__ __forceinline__ void ln_row(const float* __restrict__ x,
                                       const float* __restrict__ g,
                                       const float* __restrict__ b,
                                       __half* __restrict__ o, int row, int tid,
                                       float* ss, float* qs) {
    const float4* xr = (const float4*)(x + (size_t)row * C_DIM);
    float4 v = xr[tid];
    float s = v.x + v.y + v.z + v.w;
    float q = v.x * v.x + v.y * v.y + v.z * v.z + v.w * v.w;
#pragma unroll
    for (int of = 16; of > 0; of >>= 1) {
        s += __shfl_xor_sync(0xffffffffu, s, of);
        q += __shfl_xor_sync(0xffffffffu, q, of);
    }
    if ((tid & 31) == 0) { ss[tid >> 5] = s; qs[tid >> 5] = q; }
    __syncthreads();
    float ts = 0.f, tq = 0.f;
#pragma unroll
    for (int i = 0; i < 8; i++) { ts += ss[i]; tq += qs[i]; }
    float mu = ts * (1.0f / C_DIM);
    float var = tq * (1.0f / C_DIM) - mu * mu;
    float rstd = rsqrtf(var + 1e-5f);
    float4 gg = ((const float4*)g)[tid];
    float4 bb = ((const float4*)b)[tid];
    float o0 = (v.x - mu) * rstd * gg.x + bb.x;
    float o1 = (v.y - mu) * rstd * gg.y + bb.y;
    float o2 = (v.z - mu) * rstd * gg.z + bb.z;
    float o3 = (v.w - mu) * rstd * gg.w + bb.w;
    __half2* po = (__half2*)(o + (size_t)row * C_DIM);
    po[tid * 2]     = __floats2half2_rn(o0, o1);
    po[tid * 2 + 1] = __floats2half2_rn(o2, o3);
}

__global__ void ln_half(const float* __restrict__ x, const float* __restrict__ g,
                        const float* __restrict__ b, __half* __restrict__ o) {
    __shared__ float ss[8], qs[8];
    ln_row(x, g, b, o, blockIdx.x, threadIdx.x, ss, qs);
}

// ---------------------------------------------------------------------------
// Fused prep: 6 weight transposes + ln1, ONE launch.
// Blocks [0, wstart) do 32x32 transpose tiles (256 thr as 32x8);
// blocks [wstart, wstart+M_ROWS) do ln1 rows (256 thr flat).
// ---------------------------------------------------------------------------
struct WJobs {
    const float* src[6];
    __half* dst[6];
    int K[6], N[6], start[7];
    float scale[6];
    const float* x;
    const float* ln_g;
    const float* ln_b;
    __half* ln_o;
};

__global__ void prep_all(WJobs jobs) {
    __shared__ float t[32][33];
    int bx = blockIdx.x;
    int wtotal = jobs.start[6];
    if (bx >= wtotal) {
        // LN part
        ln_row(jobs.x, jobs.ln_g, jobs.ln_b, jobs.ln_o, bx - wtotal,
               threadIdx.y * 32 + threadIdx.x, &t[0][0], &t[1][0]);
        return;
    }
    int j = 0;
#pragma unroll
    for (int i = 1; i < 6; i++)
        if (bx >= jobs.start[i]) j = i;
    int idx = bx - jobs.start[j];
    int K = jobs.K[j], N = jobs.N[j];
    int ntiles = N >> 5;
    int n0 = (idx % ntiles) * 32;
    int k0 = (idx / ntiles) * 32;
    const float* W = jobs.src[j];
    __half* T = jobs.dst[j];
    float scale = jobs.scale[j];
    int tx = threadIdx.x, ty = threadIdx.y;  // 32x8
#pragma unroll
    for (int i = 0; i < 32; i += 8) t[ty + i][tx] = W[(size_t)(k0 + ty + i) * N + n0 + tx];
    __syncthreads();
#pragma unroll
    for (int i = 0; i < 32; i += 8) {
        size_t o = (size_t)(n0 + ty + i) * K + k0 + tx;
        T[o] = __float2half_rn(t[tx][ty + i] * scale);
    }
}

// ---------------------------------------------------------------------------
// Flash attention on mma.sync fp16, fused QKV input [M, 3072].
// 128-row q-tiles, 8 warps, double-buffered K/V, f16x2 ex2 softmax
// (log2e folded into Wq). Deferred row-sum after PV issue; V prefetch LDGs
// issued before the barrier so their latency overlaps the wait.
// ---------------------------------------------------------------------------
struct ASmem {
    __half Qs[128 * 64];
    __half Ks[2][64 * 64];
    __half Vt[2][64 * 64];
};

__global__ __launch_bounds__(256, 2)
void attn_mma(const __half* __restrict__ QKV, __half* __restrict__ Og) {
    __shared__ ASmem s;
    const int qtx = blockIdx.x;
    const int NT = T_SEQ / 128;  // 16
    const int qt = (qtx & 1) ? (NT - 1 - (qtx >> 1)) : (qtx >> 1);
    const int h = blockIdx.y, b = blockIdx.z;
    const int tid = threadIdx.x;
    const int lane = tid & 31;
    const int w = tid >> 5;

    const __half* Qg = QKV + h * D_HEAD;
    const __half* Kg = QKV + C_DIM + h * D_HEAD;
    const __half* Vg = QKV + 2 * C_DIM + h * D_HEAD;

    const uint32_t sq = smem_u32(s.Qs);

    const int rowA = (lane & 7) + ((lane >> 3) & 1) * 8;
    const int colA = (lane >> 4) * 16;
    const int rowB = (lane & 7) + (lane >> 4) * 8;
    const int colB = ((lane >> 3) & 1) * 16;

    {
        int r = tid >> 1, hh = (tid & 1) * 64;
        const char* src = (const char*)(Qg + ((size_t)(b * T_SEQ + qt * 128 + r)) * QKV_N) + hh;
#pragma unroll
        for (int j = 0; j < 4; j++)
            cp16(sq + SWZ((uint32_t)(r * 128 + hh + j * 16)), src + j * 16);
        cp_commit();
    }
    cp_wait<0>();
    __syncthreads();

    uint32_t qa[4][4];
#pragma unroll
    for (int ks = 0; ks < 4; ks++)
        ldsm4(qa[ks], sq + SWZ((uint32_t)((w * 16 + rowA) * 128 + ks * 32 + colA)));

    const int kr = tid >> 2, kq = (tid & 3) * 32;
    auto issueK = [&](int kt, int buf) {
        const uint32_t skb = smem_u32(s.Ks[buf]);
        const char* src = (const char*)(Kg + ((size_t)(b * T_SEQ + kt * 64 + kr)) * QKV_N) + kq;
#pragma unroll
        for (int j = 0; j < 2; j++)
            cp16(skb + SWZ((uint32_t)(kr * 128 + kq + j * 16)), src + j * 16);
        cp_commit();
    };
    const int vkp = lane * 2;
    const int vd0 = w * 8;
    __half va0[8], va1[8];
    auto loadV = [&](int kt) {
        const uint4* p0 = (const uint4*)(Vg + ((size_t)(b * T_SEQ + kt * 64 + vkp)) * QKV_N + vd0);
        const uint4* p1 = (const uint4*)(Vg + ((size_t)(b * T_SEQ + kt * 64 + vkp + 1)) * QKV_N + vd0);
        *(uint4*)(va0) = p0[0];
        *(uint4*)(va1) = p1[0];
    };
    issueK(0, 0);
    loadV(0);

    float m0 = -1e30f, m1 = -1e30f, l0 = 0.f, l1 = 0.f;
    float oacc[8][4];
#pragma unroll
    for (int nt = 0; nt < 8; nt++)
#pragma unroll
        for (int r = 0; r < 4; r++) oacc[nt][r] = 0.f;

    const int nkt = 2 * qt + 2;
    for (int kt = 0; kt < nkt; kt++) {
        const int buf = kt & 1;
        cp_wait<0>();
        {
            char* svp = (char*)s.Vt[buf];
#pragma unroll
            for (int i = 0; i < 8; i++) {
                int d = vd0 + i;
                *(__half2*)(svp + SWZ((uint32_t)(d * 128 + vkp * 2))) = __halves2half2(va0[i], va1[i]);
            }
        }
        if (kt + 1 < nkt) loadV(kt + 1);
        __syncthreads();

        if (kt + 1 < nkt) issueK(kt + 1, buf ^ 1);

        const uint32_t sk = smem_u32(s.Ks[buf]);
        const uint32_t sv = smem_u32(s.Vt[buf]);

        // S = Q @ K^T
        float sacc[8][4];
#pragma unroll
        for (int nt = 0; nt < 8; nt++)
#pragma unroll
            for (int r = 0; r < 4; r++) sacc[nt][r] = 0.f;
#pragma unroll
        for (int ks = 0; ks < 4; ks++) {
            uint32_t kb[4][4];
#pragma unroll
            for (int p = 0; p < 4; p++)
                ldsm4(kb[p], sk + SWZ((uint32_t)((p * 16 + rowB) * 128 + ks * 32 + colB)));
#pragma unroll
            for (int nt = 0; nt < 8; nt++)
                mma_f16(sacc[nt], qa[ks], kb[nt >> 1][(nt & 1) * 2], kb[nt >> 1][(nt & 1) * 2 + 1]);
        }

        // causal mask (only diagonal-crossing tiles)
        if (kt >= 2 * qt) {
            int grow0 = qt * 128 + w * 16 + (lane >> 2);
            int grow1 = grow0 + 8;
            int gc0 = kt * 64 + 2 * (lane & 3);
#pragma unroll
            for (int nt = 0; nt < 8; nt++) {
                int cl = gc0 + nt * 8;
                if (cl > grow0)     sacc[nt][0] = -1e30f;
                if (cl + 1 > grow0) sacc[nt][1] = -1e30f;
                if (cl > grow1)     sacc[nt][2] = -1e30f;
                if (cl + 1 > grow1) sacc[nt][3] = -1e30f;
            }
        }

        // row max
        float mx0 = -1e30f, mx1 = -1e30f;
#pragma unroll
        for (int nt = 0; nt < 8; nt++) {
            mx0 = fmaxf(mx0, fmaxf(sacc[nt][0], sacc[nt][1]));
            mx1 = fmaxf(mx1, fmaxf(sacc[nt][2], sacc[nt][3]));
        }
        mx0 = fmaxf(mx0, __shfl_xor_sync(0xffffffffu, mx0, 1));
        mx0 = fmaxf(mx0, __shfl_xor_sync(0xffffffffu, mx0, 2));
        mx1 = fmaxf(mx1, __shfl_xor_sync(0xffffffffu, mx1, 1));
        mx1 = fmaxf(mx1, __shfl_xor_sync(0xffffffffu, mx1, 2));
        float mn0 = fmaxf(m0, mx0), mn1 = fmaxf(m1, mx1);
        float al0 = ex2(m0 - mn0), al1 = ex2(m1 - mn1);
        m0 = mn0; m1 = mn1;

        // O rescale BEFORE PV accumulation (skip if no row max moved)
        if (!__all_sync(0xffffffffu, (al0 == 1.0f) && (al1 == 1.0f))) {
#pragma unroll
            for (int nt = 0; nt < 8; nt++) {
                oacc[nt][0] *= al0; oacc[nt][1] *= al0;
                oacc[nt][2] *= al1; oacc[nt][3] *= al1;
            }
        }

        // P = 2^(S-m) via f16x2 ex2 -> mma A-fragments (no sum yet)
        uint32_t pfrag[4][4];
#pragma unroll
        for (int ks = 0; ks < 4; ks++) {
#pragma unroll
            for (int j = 0; j < 2; j++) {
                int nt = 2 * ks + j;
                pfrag[ks][j * 2 + 0] = h2ex2(packh2(sacc[nt][0] - mn0, sacc[nt][1] - mn0));
                pfrag[ks][j * 2 + 1] = h2ex2(packh2(sacc[nt][2] - mn1, sacc[nt][3] - mn1));
            }
        }

        // O += P @ V  (issued before the sum reduction)
#pragma unroll
        for (int ks = 0; ks < 4; ks++) {
            uint32_t vb[4][4];
#pragma unroll
            for (int p = 0; p < 4; p++)
                ldsm4(vb[p], sv + SWZ((uint32_t)((p * 16 + rowB) * 128 + ks * 32 + colB)));
#pragma unroll
            for (int nt = 0; nt < 8; nt++)
                mma_f16(oacc[nt], pfrag[ks], vb[nt >> 1][(nt & 1) * 2], vb[nt >> 1][(nt & 1) * 2 + 1]);
        }

        // deferred row-sum + l update (overlaps the in-flight PV mmas)
        float s0 = 0.f, s1 = 0.f;
#pragma unroll
        for (int ks = 0; ks < 4; ks++) {
#pragma unroll
            for (int j = 0; j < 2; j++) {
                float2 f0 = __half22float2(*(__half2*)&pfrag[ks][j * 2 + 0]);
                float2 f1 = __half22float2(*(__half2*)&pfrag[ks][j * 2 + 1]);
                s0 += f0.x + f0.y;
                s1 += f1.x + f1.y;
            }
        }
        s0 += __shfl_xor_sync(0xffffffffu, s0, 1);
        s0 += __shfl_xor_sync(0xffffffffu, s0, 2);
        s1 += __shfl_xor_sync(0xffffffffu, s1, 1);
        s1 += __shfl_xor_sync(0xffffffffu, s1, 2);
        l0 = l0 * al0 + s0;
        l1 = l1 * al1 + s1;
    }

    float inv0 = 1.0f / l0, inv1 = 1.0f / l1;
    int row0 = qt * 128 + w * 16 + (lane >> 2);
    int row1 = row0 + 8;
#pragma unroll
    for (int nt = 0; nt < 8; nt++) {
        int col = h * D_HEAD + nt * 8 + 2 * (lane & 3);
        *(__half2*)(Og + ((size_t)(b * T_SEQ + row0)) * C_DIM + col) =
            __floats2half2_rn(oacc[nt][0] * inv0, oacc[nt][1] * inv0);
        *(__half2*)(Og + ((size_t)(b * T_SEQ + row1)) * C_DIM + col) =
            __floats2half2_rn(oacc[nt][2] * inv1, oacc[nt][3] * inv1);
    }
}

// ---------------------------------------------------------------------------
// Launch
// ---------------------------------------------------------------------------
extern "C" void kernel_launch(void* const* d_in, const int* in_sizes, int n_in,
                              void* d_out, int out_size) {
    const float* x    = (const float*)d_in[0];
    const float* Wq   = (const float*)d_in[1];
    const float* Wk   = (const float*)d_in[2];
    const float* Wv   = (const float*)d_in[3];
    const float* Wo   = (const float*)d_in[4];
    const float* bo   = (const float*)d_in[5];
    const float* ln1g = (const float*)d_in[6];
    const float* ln1b = (const float*)d_in[7];
    const float* ln2g = (const float*)d_in[8];
    const float* ln2b = (const float*)d_in[9];
    const float* W1   = (const float*)d_in[10];
    const float* b1   = (const float*)d_in[11];
    const float* W2   = (const float*)d_in[12];
    const float* b2   = (const float*)d_in[13];
    float* out = (float*)d_out;

    __half *a, *qkv, *at, *ffh;
    float* x2;
    __half *wqkv, *wo, *w1, *w2;
    cudaGetSymbolAddress((void**)&a,    g_a);
    cudaGetSymbolAddress((void**)&qkv,  g_qkv);
    cudaGetSymbolAddress((void**)&at,   g_at);
    cudaGetSymbolAddress((void**)&ffh,  g_ffh);
    cudaGetSymbolAddress((void**)&x2,   g_x2);
    cudaGetSymbolAddress((void**)&wqkv, g_wqkv);
    cudaGetSymbolAddress((void**)&wo,   g_wo);
    cudaGetSymbolAddress((void**)&w1,   g_w1);
    cudaGetSymbolAddress((void**)&w2,   g_w2);

    cudaFuncSetAttribute(gemm_mma<0, 0>, cudaFuncAttributeMaxDynamicSharedMemorySize, GEMM_SMEM);
    cudaFuncSetAttribute(gemm_mma<0, 1>, cudaFuncAttributeMaxDynamicSharedMemorySize, GEMM_SMEM);
    cudaFuncSetAttribute(gemm_mma<1, 1>, cudaFuncAttributeMaxDynamicSharedMemorySize, GEMM_SMEM);

    dim3 gQKV(QKV_N / 128, M_ROWS / 128);
    dim3 g1024(C_DIM / 128, M_ROWS / 128);
    dim3 g4096(FF_DIM / 128, M_ROWS / 128);

    // fused prep: all 6 weight transposes + ln1, one launch.
    // Wq scaled by (1/8)*log2(e) so softmax uses raw exp2.
    WJobs jobs;
    jobs.src[0] = Wq; jobs.dst[0] = wqkv;                     jobs.K[0] = C_DIM;  jobs.N[0] = C_DIM;  jobs.scale[0] = 0.125f * 1.44269504089f;
    jobs.src[1] = Wk; jobs.dst[1] = wqkv + C_DIM * C_DIM;     jobs.K[1] = C_DIM;  jobs.N[1] = C_DIM;  jobs.scale[1] = 1.0f;
    jobs.src[2] = Wv; jobs.dst[2] = wqkv + 2 * C_DIM * C_DIM; jobs.K[2] = C_DIM;  jobs.N[2] = C_DIM;  jobs.scale[2] = 1.0f;
    jobs.src[3] = Wo; jobs.dst[3] = wo;                       jobs.K[3] = C_DIM;  jobs.N[3] = C_DIM;  jobs.scale[3] = 1.0f;
    jobs.src[4] = W1; jobs.dst[4] = w1;                       jobs.K[4] = C_DIM;  jobs.N[4] = FF_DIM; jobs.scale[4] = 1.0f;
    jobs.src[5] = W2; jobs.dst[5] = w2;                       jobs.K[5] = FF_DIM; jobs.N[5] = C_DIM;  jobs.scale[5] = 1.0f;
    jobs.x = x; jobs.ln_g = ln1g; jobs.ln_b = ln1b; jobs.ln_o = a;
    int acc = 0;
    for (int i = 0; i < 6; i++) {
        jobs.start[i] = acc;
        acc += (jobs.N[i] >> 5) * (jobs.K[i] >> 5);
    }
    jobs.start[6] = acc;
    prep_all<<<acc + M_ROWS, dim3(32, 8)>>>(jobs);

    // fused QKV projection (fp16 out)
    gemm_mma<0, 1><<<gQKV, 256, GEMM_SMEM>>>(a, wqkv, nullptr, nullptr,
                                             nullptr, qkv, QKV_N, C_DIM);
    // flash attention (fp16 tensor cores, deferred-sum exp2 softmax)
    attn_mma<<<dim3(T_SEQ / 128, H_NUM, B_NUM), 256>>>(qkv, at);
    // Wo projection + bias + residual -> x2 (fp32)
    gemm_mma<0, 0><<<g1024, 256, GEMM_SMEM>>>(at, wo, bo, x,
                                              x2, nullptr, C_DIM, C_DIM);
    // ln2 -> fp16
    ln_half<<<M_ROWS, 256>>>(x2, ln2g, ln2b, a);
    // MLP up + bias + ReLU (fp16 out)
    gemm_mma<1, 1><<<g4096, 256, GEMM_SMEM>>>(a, w1, b1, nullptr,
                                              nullptr, ffh, FF_DIM, C_DIM);
    // MLP down + bias + residual -> out (fp32)
    gemm_mma<0, 0><<<g1024, 256, GEMM_SMEM>>>(ffh, w2, b2, x2,
                                              out, nullptr, C_DIM, FF_DIM);
}

// round 16
// speedup vs baseline: 1.0061x; 1.0061x over previous
#include <cuda_runtime.h>
#include <cuda_fp16.h>
#include <math.h>
#include <cstdint>

// ---------------------------------------------------------------------------
// MiniBlock: x + attn(ln1(x)); then + mlp(ln2(.))
// B=4, T=2048, C=1024, H=16, D=64, FF=4096.
// GEMMs: mma.sync fp16 fp32-acc, 128x128x64 tiles (legacy-HMMA issue floor).
// Attention: flash, 128-row q-tiles, f16x2 ex2 softmax, deferred row-sum,
// V prefetch issued under the barrier wait.
// ---------------------------------------------------------------------------

#define B_NUM 4
#define T_SEQ 2048
#define C_DIM 1024
#define H_NUM 16
#define D_HEAD 64
#define FF_DIM 4096
#define M_ROWS (B_NUM * T_SEQ)   // 8192
#define QKV_N (3 * C_DIM)        // 3072

// ---------------- scratch (device globals) ----------------------------------
__device__ __half g_a  [M_ROWS * C_DIM];
__device__ __half g_qkv[M_ROWS * QKV_N];
__device__ __half g_at [M_ROWS * C_DIM];
__device__ __half g_ffh[M_ROWS * FF_DIM];
__device__ float  g_x2 [M_ROWS * C_DIM];

__device__ __half g_wqkv[QKV_N * C_DIM];
__device__ __half g_wo[C_DIM * C_DIM];
__device__ __half g_w1[FF_DIM * C_DIM];
__device__ __half g_w2[C_DIM * FF_DIM];

// ---------------- PTX helpers ------------------------------------------------
__device__ __forceinline__ uint32_t smem_u32(const void* p) {
    uint32_t a;
    asm("{ .reg .u64 t; cvta.to.shared.u64 t, %1; cvt.u32.u64 %0, t; }" : "=r"(a) : "l"(p));
    return a;
}
__device__ __forceinline__ void cp16(uint32_t dst, const void* src) {
    asm volatile("cp.async.cg.shared.global [%0], [%1], 16;" :: "r"(dst), "l"(src));
}
__device__ __forceinline__ void cp_commit() { asm volatile("cp.async.commit_group;" ::: "memory"); }
template <int N> __device__ __forceinline__ void cp_wait() {
    asm volatile("cp.async.wait_group %0;" :: "n"(N) : "memory");
}
__device__ __forceinline__ void ldsm4(uint32_t r[4], uint32_t addr) {
    asm volatile("ldmatrix.sync.aligned.m8n8.x4.shared.b16 {%0,%1,%2,%3}, [%4];"
                 : "=r"(r[0]), "=r"(r[1]), "=r"(r[2]), "=r"(r[3]) : "r"(addr));
}
__device__ __forceinline__ void mma_f16(float c[4], const uint32_t a[4],
                                        uint32_t b0, uint32_t b1) {
    asm volatile(
        "mma.sync.aligned.m16n8k16.row.col.f32.f16.f16.f32 "
        "{%0,%1,%2,%3}, {%4,%5,%6,%7}, {%8,%9}, {%0,%1,%2,%3};"
        : "+f"(c[0]), "+f"(c[1]), "+f"(c[2]), "+f"(c[3])
        : "r"(a[0]), "r"(a[1]), "r"(a[2]), "r"(a[3]), "r"(b0), "r"(b1));
}
__device__ __forceinline__ uint32_t packh2(float a, float b) {
    __half2 h = __floats2half2_rn(a, b);
    return *(uint32_t*)&h;
}
__device__ __forceinline__ float ex2(float x) {
    float y;
    asm("ex2.approx.f32 %0, %1;" : "=f"(y) : "f"(x));
    return y;
}
__device__ __forceinline__ uint32_t h2ex2(uint32_t x) {
    uint32_t y;
    asm("ex2.approx.f16x2 %0, %1;" : "=r"(y) : "r"(x));
    return y;
}

#define SWZ(x) ((x) ^ (((x) >> 3) & 0x70))

// ---------------------------------------------------------------------------
// fp16 GEMM: C[M,N] = A[M,K] @ B^T   (B stored [N,K] fp16)
// Block 128x128x64, 256 thr (8 warps 2x4), warp tile 64x32.
// 3-stage cp.async pipeline, 2 CTAs/SM.  (At the mma.sync issue floor.)
// ---------------------------------------------------------------------------
static constexpr int GEMM_STAGE = 32768;
static constexpr int GEMM_SMEM  = 3 * GEMM_STAGE;  // 98304

template <int RELU, int OUT_HALF>
__global__ __launch_bounds__(256, 2)
void gemm_mma(const __half* __restrict__ A, const __half* __restrict__ B,
              const float* __restrict__ bias, const float* __restrict__ res,
              float* __restrict__ Cf, __half* __restrict__ Oh,
              int N, int K) {
    extern __shared__ __align__(1024) char smem[];
    const uint32_t sb = smem_u32(smem);
    const int tid = threadIdx.x;
    const int lane = tid & 31;
    const int wid = tid >> 5;
    const int warp_m = wid >> 2;
    const int warp_n = wid & 3;
    const int n0 = blockIdx.x * 128;
    const int m0 = blockIdx.y * 128;
    const int nc = K >> 6;

    const int lrow = tid >> 1;
    const int lhalf = (tid & 1) * 64;
    const char* pa = (const char*)(A + (size_t)(m0 + lrow) * K) + lhalf;
    const char* pb = (const char*)(B + (size_t)(n0 + lrow) * K) + lhalf;

    auto issue = [&](int c) {
        uint32_t base = sb + (uint32_t)(c % 3) * GEMM_STAGE;
        size_t koff = (size_t)(c << 6) * 2;
#pragma unroll
        for (int j = 0; j < 4; j++) {
            uint32_t so = SWZ((uint32_t)(lrow * 128 + lhalf + j * 16));
            cp16(base + so,         pa + koff + j * 16);
            cp16(base + 16384 + so, pb + koff + j * 16);
        }
        cp_commit();
    };

    issue(0);
    if (nc > 1) issue(1);

    const int rowA = (lane & 7) + ((lane >> 3) & 1) * 8;
    const int colA = (lane >> 4) * 16;
    const int rowB = (lane & 7) + (lane >> 4) * 8;
    const int colB = ((lane >> 3) & 1) * 16;

    float acc[4][4][4];
#pragma unroll
    for (int a = 0; a < 4; a++)
#pragma unroll
        for (int b = 0; b < 4; b++)
#pragma unroll
            for (int r = 0; r < 4; r++) acc[a][b][r] = 0.f;

    for (int c = 0; c < nc; c++) {
        if (c + 1 < nc) cp_wait<1>(); else cp_wait<0>();
        __syncthreads();
        if (c + 2 < nc) issue(c + 2);

        uint32_t stb = sb + (uint32_t)(c % 3) * GEMM_STAGE;
#pragma unroll
        for (int ks = 0; ks < 4; ks++) {
            uint32_t ah[4][4], bh[2][4];
#pragma unroll
            for (int mt = 0; mt < 4; mt++) {
                uint32_t sw = SWZ((uint32_t)((warp_m * 64 + mt * 16 + rowA) * 128 + ks * 32 + colA));
                ldsm4(ah[mt], stb + sw);
            }
#pragma unroll
            for (int np = 0; np < 2; np++) {
                uint32_t sw = SWZ((uint32_t)((warp_n * 32 + np * 16 + rowB) * 128 + ks * 32 + colB));
                ldsm4(bh[np], stb + 16384 + sw);
            }
#pragma unroll
            for (int mt = 0; mt < 4; mt++)
#pragma unroll
                for (int nt = 0; nt < 4; nt++)
                    mma_f16(acc[mt][nt], ah[mt],
                            bh[nt >> 1][(nt & 1) * 2], bh[nt >> 1][(nt & 1) * 2 + 1]);
        }
    }

    const int rbase = m0 + warp_m * 64 + (lane >> 2);
    const int cbase = n0 + warp_n * 32 + (lane & 3) * 2;

    // bias is column-only: hoist the 4 loads out of the row loops
    float2 bcol[4];
#pragma unroll
    for (int nt = 0; nt < 4; nt++) {
        if (bias) bcol[nt] = *(const float2*)(bias + cbase + nt * 8);
        else { bcol[nt].x = 0.f; bcol[nt].y = 0.f; }
    }

#pragma unroll
    for (int mt = 0; mt < 4; mt++) {
#pragma unroll
        for (int nt = 0; nt < 4; nt++) {
            int col = cbase + nt * 8;
#pragma unroll
            for (int half = 0; half < 2; half++) {
                int row = rbase + mt * 16 + half * 8;
                float v0 = acc[mt][nt][half * 2 + 0] + bcol[nt].x;
                float v1 = acc[mt][nt][half * 2 + 1] + bcol[nt].y;
                if (res) {
                    float2 r2 = *(const float2*)(res + (size_t)row * N + col);
                    v0 += r2.x; v1 += r2.y;
                }
                if (RELU) { v0 = fmaxf(v0, 0.f); v1 = fmaxf(v1, 0.f); }
                if (OUT_HALF) {
                    __half2 h = __floats2half2_rn(v0, v1);
                    *(__half2*)(Oh + (size_t)row * N + col) = h;
                } else {
                    float2 o2; o2.x = v0; o2.y = v1;
                    *(float2*)(Cf + (size_t)row * N + col) = o2;
                }
            }
        }
    }
}

// ---------------------------------------------------------------------------
// LayerNorm -> fp16 output. One block per row, 256 threads.
// ---------------------------------------------------------------------------
__global__ void ln_half(const float* __restrict__ x, const float* __restrict__ g,
                        const float* __restrict__ b, __half* __restrict__ o) {
    int row = blockIdx.x;
    int tid = threadIdx.x;
    const float4* xr = (const float4*)(x + (size_t)row * C_DIM);
    float4 v = xr[tid];
    float s = v.x + v.y + v.z + v.w;
    float q = v.x * v.x + v.y * v.y + v.z * v.z + v.w * v.w;
#pragma unroll
    for (int of = 16; of > 0; of >>= 1) {
        s += __shfl_xor_sync(0xffffffffu, s, of);
        q += __shfl_xor_sync(0xffffffffu, q, of);
    }
    __shared__ float ss[8], qs[8];
    if ((tid & 31) == 0) { ss[tid >> 5] = s; qs[tid >> 5] = q; }
    __syncthreads();
    float ts = 0.f, tq = 0.f;
#pragma unroll
    for (int i = 0; i < 8; i++) { ts += ss[i]; tq += qs[i]; }
    float mu = ts * (1.0f / C_DIM);
    float var = tq * (1.0f / C_DIM) - mu * mu;
    float rstd = rsqrtf(var + 1e-5f);
    float4 gg = ((const float4*)g)[tid];
    float4 bb = ((const float4*)b)[tid];
    float o0 = (v.x - mu) * rstd * gg.x + bb.x;
    float o1 = (v.y - mu) * rstd * gg.y + bb.y;
    float o2 = (v.z - mu) * rstd * gg.z + bb.z;
    float o3 = (v.w - mu) * rstd * gg.w + bb.w;
    __half2* po = (__half2*)(o + (size_t)row * C_DIM);
    po[tid * 2]     = __floats2half2_rn(o0, o1);
    po[tid * 2 + 1] = __floats2half2_rn(o2, o3);
}

// ---------------------------------------------------------------------------
// Batched weight transpose (+scale): all 6 weights in ONE launch.
// ---------------------------------------------------------------------------
struct WJobs {
    const float* src[6];
    __half* dst[6];
    int K[6], N[6], start[7];
    float scale[6];
};

__global__ void wtrans_all(WJobs jobs) {
    __shared__ float t[32][33];
    int bx = blockIdx.x;
    int j = 0;
#pragma unroll
    for (int i = 1; i < 6; i++)
        if (bx >= jobs.start[i]) j = i;
    int idx = bx - jobs.start[j];
    int K = jobs.K[j], N = jobs.N[j];
    int ntiles = N >> 5;
    int n0 = (idx % ntiles) * 32;
    int k0 = (idx / ntiles) * 32;
    const float* W = jobs.src[j];
    __half* T = jobs.dst[j];
    float scale = jobs.scale[j];
    int tx = threadIdx.x, ty = threadIdx.y;  // 32x8
#pragma unroll
    for (int i = 0; i < 32; i += 8) t[ty + i][tx] = W[(size_t)(k0 + ty + i) * N + n0 + tx];
    __syncthreads();
#pragma unroll
    for (int i = 0; i < 32; i += 8) {
        size_t o = (size_t)(n0 + ty + i) * K + k0 + tx;
        T[o] = __float2half_rn(t[tx][ty + i] * scale);
    }
}

// ---------------------------------------------------------------------------
// Flash attention on mma.sync fp16, fused QKV input [M, 3072].
// 128-row q-tiles, 8 warps, double-buffered K/V, f16x2 ex2 softmax
// (log2e folded into Wq). Deferred row-sum after PV issue; V prefetch LDGs
// issued before the barrier so their latency overlaps the wait.
// ---------------------------------------------------------------------------
struct ASmem {
    __half Qs[128 * 64];
    __half Ks[2][64 * 64];
    __half Vt[2][64 * 64];
};

__global__ __launch_bounds__(256, 2)
void attn_mma(const __half* __restrict__ QKV, __half* __restrict__ Og) {
    __shared__ ASmem s;
    const int qtx = blockIdx.x;
    const int NT = T_SEQ / 128;  // 16
    const int qt = (qtx & 1) ? (NT - 1 - (qtx >> 1)) : (qtx >> 1);
    const int h = blockIdx.y, b = blockIdx.z;
    const int tid = threadIdx.x;
    const int lane = tid & 31;
    const int w = tid >> 5;

    const __half* Qg = QKV + h * D_HEAD;
    const __half* Kg = QKV + C_DIM + h * D_HEAD;
    const __half* Vg = QKV + 2 * C_DIM + h * D_HEAD;

    const uint32_t sq = smem_u32(s.Qs);

    const int rowA = (lane & 7) + ((lane >> 3) & 1) * 8;
    const int colA = (lane >> 4) * 16;
    const int rowB = (lane & 7) + (lane >> 4) * 8;
    const int colB = ((lane >> 3) & 1) * 16;

    {
        int r = tid >> 1, hh = (tid & 1) * 64;
        const char* src = (const char*)(Qg + ((size_t)(b * T_SEQ + qt * 128 + r)) * QKV_N) + hh;
#pragma unroll
        for (int j = 0; j < 4; j++)
            cp16(sq + SWZ((uint32_t)(r * 128 + hh + j * 16)), src + j * 16);
        cp_commit();
    }
    cp_wait<0>();
    __syncthreads();

    uint32_t qa[4][4];
#pragma unroll
    for (int ks = 0; ks < 4; ks++)
        ldsm4(qa[ks], sq + SWZ((uint32_t)((w * 16 + rowA) * 128 + ks * 32 + colA)));

    const int kr = tid >> 2, kq = (tid & 3) * 32;
    auto issueK = [&](int kt, int buf) {
        const uint32_t skb = smem_u32(s.Ks[buf]);
        const char* src = (const char*)(Kg + ((size_t)(b * T_SEQ + kt * 64 + kr)) * QKV_N) + kq;
#pragma unroll
        for (int j = 0; j < 2; j++)
            cp16(skb + SWZ((uint32_t)(kr * 128 + kq + j * 16)), src + j * 16);
        cp_commit();
    };
    const int vkp = lane * 2;
    const int vd0 = w * 8;
    __half va0[8], va1[8];
    auto loadV = [&](int kt) {
        const uint4* p0 = (const uint4*)(Vg + ((size_t)(b * T_SEQ + kt * 64 + vkp)) * QKV_N + vd0);
        const uint4* p1 = (const uint4*)(Vg + ((size_t)(b * T_SEQ + kt * 64 + vkp + 1)) * QKV_N + vd0);
        *(uint4*)(va0) = p0[0];
        *(uint4*)(va1) = p1[0];
    };
    issueK(0, 0);
    loadV(0);

    float m0 = -1e30f, m1 = -1e30f, l0 = 0.f, l1 = 0.f;
    float oacc[8][4];
#pragma unroll
    for (int nt = 0; nt < 8; nt++)
#pragma unroll
        for (int r = 0; r < 4; r++) oacc[nt][r] = 0.f;

    const int nkt = 2 * qt + 2;
    for (int kt = 0; kt < nkt; kt++) {
        const int buf = kt & 1;
        cp_wait<0>();
        {
            char* svp = (char*)s.Vt[buf];
#pragma unroll
            for (int i = 0; i < 8; i++) {
                int d = vd0 + i;
                *(__half2*)(svp + SWZ((uint32_t)(d * 128 + vkp * 2))) = __halves2half2(va0[i], va1[i]);
            }
        }
        if (kt + 1 < nkt) loadV(kt + 1);
        __syncthreads();

        if (kt + 1 < nkt) issueK(kt + 1, buf ^ 1);

        const uint32_t sk = smem_u32(s.Ks[buf]);
        const uint32_t sv = smem_u32(s.Vt[buf]);

        // S = Q @ K^T
        float sacc[8][4];
#pragma unroll
        for (int nt = 0; nt < 8; nt++)
#pragma unroll
            for (int r = 0; r < 4; r++) sacc[nt][r] = 0.f;
#pragma unroll
        for (int ks = 0; ks < 4; ks++) {
            uint32_t kb[4][4];
#pragma unroll
            for (int p = 0; p < 4; p++)
                ldsm4(kb[p], sk + SWZ((uint32_t)((p * 16 + rowB) * 128 + ks * 32 + colB)));
#pragma unroll
            for (int nt = 0; nt < 8; nt++)
                mma_f16(sacc[nt], qa[ks], kb[nt >> 1][(nt & 1) * 2], kb[nt >> 1][(nt & 1) * 2 + 1]);
        }

        // causal mask (only diagonal-crossing tiles)
        if (kt >= 2 * qt) {
            int grow0 = qt * 128 + w * 16 + (lane >> 2);
            int grow1 = grow0 + 8;
            int gc0 = kt * 64 + 2 * (lane & 3);
#pragma unroll
            for (int nt = 0; nt < 8; nt++) {
                int cl = gc0 + nt * 8;
                if (cl > grow0)     sacc[nt][0] = -1e30f;
                if (cl + 1 > grow0) sacc[nt][1] = -1e30f;
                if (cl > grow1)     sacc[nt][2] = -1e30f;
                if (cl + 1 > grow1) sacc[nt][3] = -1e30f;
            }
        }

        // row max
        float mx0 = -1e30f, mx1 = -1e30f;
#pragma unroll
        for (int nt = 0; nt < 8; nt++) {
            mx0 = fmaxf(mx0, fmaxf(sacc[nt][0], sacc[nt][1]));
            mx1 = fmaxf(mx1, fmaxf(sacc[nt][2], sacc[nt][3]));
        }
        mx0 = fmaxf(mx0, __shfl_xor_sync(0xffffffffu, mx0, 1));
        mx0 = fmaxf(mx0, __shfl_xor_sync(0xffffffffu, mx0, 2));
        mx1 = fmaxf(mx1, __shfl_xor_sync(0xffffffffu, mx1, 1));
        mx1 = fmaxf(mx1, __shfl_xor_sync(0xffffffffu, mx1, 2));
        float mn0 = fmaxf(m0, mx0), mn1 = fmaxf(m1, mx1);
        float al0 = ex2(m0 - mn0), al1 = ex2(m1 - mn1);
        m0 = mn0; m1 = mn1;

        // O rescale BEFORE PV accumulation (skip if no row max moved)
        if (!__all_sync(0xffffffffu, (al0 == 1.0f) && (al1 == 1.0f))) {
#pragma unroll
            for (int nt = 0; nt < 8; nt++) {
                oacc[nt][0] *= al0; oacc[nt][1] *= al0;
                oacc[nt][2] *= al1; oacc[nt][3] *= al1;
            }
        }

        // P = 2^(S-m) via f16x2 ex2 -> mma A-fragments (no sum yet)
        uint32_t pfrag[4][4];
#pragma unroll
        for (int ks = 0; ks < 4; ks++) {
#pragma unroll
            for (int j = 0; j < 2; j++) {
                int nt = 2 * ks + j;
                pfrag[ks][j * 2 + 0] = h2ex2(packh2(sacc[nt][0] - mn0, sacc[nt][1] - mn0));
                pfrag[ks][j * 2 + 1] = h2ex2(packh2(sacc[nt][2] - mn1, sacc[nt][3] - mn1));
            }
        }

        // O += P @ V  (issued before the sum reduction)
#pragma unroll
        for (int ks = 0; ks < 4; ks++) {
            uint32_t vb[4][4];
#pragma unroll
            for (int p = 0; p < 4; p++)
                ldsm4(vb[p], sv + SWZ((uint32_t)((p * 16 + rowB) * 128 + ks * 32 + colB)));
#pragma unroll
            for (int nt = 0; nt < 8; nt++)
                mma_f16(oacc[nt], pfrag[ks], vb[nt >> 1][(nt & 1) * 2], vb[nt >> 1][(nt & 1) * 2 + 1]);
        }

        // deferred row-sum + l update (overlaps the in-flight PV mmas)
        float s0 = 0.f, s1 = 0.f;
#pragma unroll
        for (int ks = 0; ks < 4; ks++) {
#pragma unroll
            for (int j = 0; j < 2; j++) {
                float2 f0 = __half22float2(*(__half2*)&pfrag[ks][j * 2 + 0]);
                float2 f1 = __half22float2(*(__half2*)&pfrag[ks][j * 2 + 1]);
                s0 += f0.x + f0.y;
                s1 += f1.x + f1.y;
            }
        }
        s0 += __shfl_xor_sync(0xffffffffu, s0, 1);
        s0 += __shfl_xor_sync(0xffffffffu, s0, 2);
        s1 += __shfl_xor_sync(0xffffffffu, s1, 1);
        s1 += __shfl_xor_sync(0xffffffffu, s1, 2);
        l0 = l0 * al0 + s0;
        l1 = l1 * al1 + s1;
    }

    float inv0 = 1.0f / l0, inv1 = 1.0f / l1;
    int row0 = qt * 128 + w * 16 + (lane >> 2);
    int row1 = row0 + 8;
#pragma unroll
    for (int nt = 0; nt < 8; nt++) {
        int col = h * D_HEAD + nt * 8 + 2 * (lane & 3);
        *(__half2*)(Og + ((size_t)(b * T_SEQ + row0)) * C_DIM + col) =
            __floats2half2_rn(oacc[nt][0] * inv0, oacc[nt][1] * inv0);
        *(__half2*)(Og + ((size_t)(b * T_SEQ + row1)) * C_DIM + col) =
            __floats2half2_rn(oacc[nt][2] * inv1, oacc[nt][3] * inv1);
    }
}

// ---------------------------------------------------------------------------
// Launch
// ---------------------------------------------------------------------------
extern "C" void kernel_launch(void* const* d_in, const int* in_sizes, int n_in,
                              void* d_out, int out_size) {
    const float* x    = (const float*)d_in[0];
    const float* Wq   = (const float*)d_in[1];
    const float* Wk   = (const float*)d_in[2];
    const float* Wv   = (const float*)d_in[3];
    const float* Wo   = (const float*)d_in[4];
    const float* bo   = (const float*)d_in[5];
    const float* ln1g = (const float*)d_in[6];
    const float* ln1b = (const float*)d_in[7];
    const float* ln2g = (const float*)d_in[8];
    const float* ln2b = (const float*)d_in[9];
    const float* W1   = (const float*)d_in[10];
    const float* b1   = (const float*)d_in[11];
    const float* W2   = (const float*)d_in[12];
    const float* b2   = (const float*)d_in[13];
    float* out = (float*)d_out;

    __half *a, *qkv, *at, *ffh;
    float* x2;
    __half *wqkv, *wo, *w1, *w2;
    cudaGetSymbolAddress((void**)&a,    g_a);
    cudaGetSymbolAddress((void**)&qkv,  g_qkv);
    cudaGetSymbolAddress((void**)&at,   g_at);
    cudaGetSymbolAddress((void**)&ffh,  g_ffh);
    cudaGetSymbolAddress((void**)&x2,   g_x2);
    cudaGetSymbolAddress((void**)&wqkv, g_wqkv);
    cudaGetSymbolAddress((void**)&wo,   g_wo);
    cudaGetSymbolAddress((void**)&w1,   g_w1);
    cudaGetSymbolAddress((void**)&w2,   g_w2);

    cudaFuncSetAttribute(gemm_mma<0, 0>, cudaFuncAttributeMaxDynamicSharedMemorySize, GEMM_SMEM);
    cudaFuncSetAttribute(gemm_mma<0, 1>, cudaFuncAttributeMaxDynamicSharedMemorySize, GEMM_SMEM);
    cudaFuncSetAttribute(gemm_mma<1, 1>, cudaFuncAttributeMaxDynamicSharedMemorySize, GEMM_SMEM);

    dim3 gQKV(QKV_N / 128, M_ROWS / 128);
    dim3 g1024(C_DIM / 128, M_ROWS / 128);
    dim3 g4096(FF_DIM / 128, M_ROWS / 128);

    // all 6 weight transposes in one launch.
    // Wq scaled by (1/8)*log2(e) so softmax uses raw exp2.
    WJobs jobs;
    jobs.src[0] = Wq; jobs.dst[0] = wqkv;                     jobs.K[0] = C_DIM;  jobs.N[0] = C_DIM;  jobs.scale[0] = 0.125f * 1.44269504089f;
    jobs.src[1] = Wk; jobs.dst[1] = wqkv + C_DIM * C_DIM;     jobs.K[1] = C_DIM;  jobs.N[1] = C_DIM;  jobs.scale[1] = 1.0f;
    jobs.src[2] = Wv; jobs.dst[2] = wqkv + 2 * C_DIM * C_DIM; jobs.K[2] = C_DIM;  jobs.N[2] = C_DIM;  jobs.scale[2] = 1.0f;
    jobs.src[3] = Wo; jobs.dst[3] = wo;                       jobs.K[3] = C_DIM;  jobs.N[3] = C_DIM;  jobs.scale[3] = 1.0f;
    jobs.src[4] = W1; jobs.dst[4] = w1;                       jobs.K[4] = C_DIM;  jobs.N[4] = FF_DIM; jobs.scale[4] = 1.0f;
    jobs.src[5] = W2; jobs.dst[5] = w2;                       jobs.K[5] = FF_DIM; jobs.N[5] = C_DIM;  jobs.scale[5] = 1.0f;
    int acc = 0;
    for (int i = 0; i < 6; i++) {
        jobs.start[i] = acc;
        acc += (jobs.N[i] >> 5) * (jobs.K[i] >> 5);
    }
    jobs.start[6] = acc;
    wtrans_all<<<acc, dim3(32, 8)>>>(jobs);

    // ln1 -> fp16 activations
    ln_half<<<M_ROWS, 256>>>(x, ln1g, ln1b, a);
    // fused QKV projection (fp16 out)
    gemm_mma<0, 1><<<gQKV, 256, GEMM_SMEM>>>(a, wqkv, nullptr, nullptr,
                                             nullptr, qkv, QKV_N, C_DIM);
    // flash attention (fp16 tensor cores, deferred-sum exp2 softmax)
    attn_mma<<<dim3(T_SEQ / 128, H_NUM, B_NUM), 256>>>(qkv, at);
    // Wo projection + bias + residual -> x2 (fp32)
    gemm_mma<0, 0><<<g1024, 256, GEMM_SMEM>>>(at, wo, bo, x,
                                              x2, nullptr, C_DIM, C_DIM);
    // ln2 -> fp16
    ln_half<<<M_ROWS, 256>>>(x2, ln2g, ln2b, a);
    // MLP up + bias + ReLU (fp16 out)
    gemm_mma<1, 1><<<g4096, 256, GEMM_SMEM>>>(a, w1, b1, nullptr,
                                              nullptr, ffh, FF_DIM, C_DIM);
    // MLP down + bias + residual -> out (fp32)
    gemm_mma<0, 0><<<g1024, 256, GEMM_SMEM>>>(ffh, w2, b2, x2,
                                              out, nullptr, C_DIM, FF_DIM);
}